// round 1
// baseline (speedup 1.0000x reference)
#include <cuda_runtime.h>
#include <math.h>

#define SS   512
#define BB   64
#define EE   512
#define HH   768
#define G4   3072      // 4*H
#define LL   32
#define SB   (SS*BB)   // 32768
#define NBLK_FWD 96

// ---------------- scratch (static device globals; allocation-free launch) --------
__device__ float g_xf [SB * G4];     // forward input-gate precompute (biases folded)
__device__ float g_xb [SB * G4];     // backward emb@Wi_b (no bias)
__device__ float g_hsf[SB * HH];     // forward hidden states
__device__ float g_hsb[SB * HH];     // backward hidden states
__device__ float g_hid[2][BB * HH];  // double-buffered recurrent hidden
__device__ float g_hTW[BB * G4];     // hT@Wh_b + bi_b + bh_b
__device__ unsigned g_bar_count;
__device__ unsigned g_bar_gen;

__device__ __forceinline__ float sigmoidf_(float x) { return 1.0f / (1.0f + expf(-x)); }

// ---------------- software grid barrier (persistent kernel) ----------------------
__device__ __forceinline__ void grid_bar(unsigned nblocks) {
    __threadfence();
    __syncthreads();
    if (threadIdx.x == 0) {
        unsigned gen = *(volatile unsigned*)&g_bar_gen;
        if (atomicAdd(&g_bar_count, 1u) == nblocks - 1u) {
            atomicExch(&g_bar_count, 0u);
            __threadfence();
            *(volatile unsigned*)&g_bar_gen = gen + 1u;
        } else {
            while (*(volatile unsigned*)&g_bar_gen == gen) { __nanosleep(64); }
        }
        __threadfence();
    }
    __syncthreads();
}

// ---------------- generic fp32 GEMM: C[M,N] = A(gathered)[M,K] @ W[K,N] + b1 + b2 --
// BM=64, BN=64, BK=16, 256 threads, 4x4 microtile. M%64==0, N%64==0, K%16==0.
__global__ void sgemm64(const float* __restrict__ A, const int* __restrict__ gather,
                        const float* __restrict__ W, int M, int N, int K,
                        const float* __restrict__ bias1, const float* __restrict__ bias2,
                        float* __restrict__ C)
{
    __shared__ __align__(16) float As[16][68];
    __shared__ __align__(16) float Bs[16][64];
    const int t  = threadIdx.x;
    const int m0 = blockIdx.y * 64;
    const int n0 = blockIdx.x * 64;
    const int c0 = 4 * (t & 15);
    const int r0 = 4 * (t >> 4);
    const int mload = t >> 2;          // 0..63
    const int kq    = (t & 3) * 4;     // 0,4,8,12
    const int nload = t & 63;
    const int kload = t >> 6;          // 0..3

    const float* arow;
    {
        int mg = m0 + mload;
        arow = gather ? (A + (size_t)gather[mg] * K) : (A + (size_t)mg * K);
    }

    float acc[4][4] = {};
    for (int k0 = 0; k0 < K; k0 += 16) {
        float4 a4 = *(const float4*)(arow + k0 + kq);
        As[kq + 0][mload] = a4.x; As[kq + 1][mload] = a4.y;
        As[kq + 2][mload] = a4.z; As[kq + 3][mload] = a4.w;
        #pragma unroll
        for (int p = 0; p < 4; p++) {
            int kk = kload + p * 4;
            Bs[kk][nload] = W[(size_t)(k0 + kk) * N + n0 + nload];
        }
        __syncthreads();
        #pragma unroll
        for (int kk = 0; kk < 16; kk++) {
            float4 a = *(const float4*)&As[kk][r0];
            float4 b = *(const float4*)&Bs[kk][c0];
            acc[0][0] += a.x*b.x; acc[0][1] += a.x*b.y; acc[0][2] += a.x*b.z; acc[0][3] += a.x*b.w;
            acc[1][0] += a.y*b.x; acc[1][1] += a.y*b.y; acc[1][2] += a.y*b.z; acc[1][3] += a.y*b.w;
            acc[2][0] += a.z*b.x; acc[2][1] += a.z*b.y; acc[2][2] += a.z*b.z; acc[2][3] += a.z*b.w;
            acc[3][0] += a.w*b.x; acc[3][1] += a.w*b.y; acc[3][2] += a.w*b.z; acc[3][3] += a.w*b.w;
        }
        __syncthreads();
    }
    float badd[4];
    #pragma unroll
    for (int j = 0; j < 4; j++) {
        float b = 0.f;
        if (bias1) b += bias1[n0 + c0 + j];
        if (bias2) b += bias2[n0 + c0 + j];
        badd[j] = b;
    }
    #pragma unroll
    for (int i = 0; i < 4; i++) {
        float4 v = make_float4(acc[i][0] + badd[0], acc[i][1] + badd[1],
                               acc[i][2] + badd[2], acc[i][3] + badd[3]);
        *(float4*)&C[(size_t)(m0 + r0 + i) * N + n0 + c0] = v;
    }
}

// ---------------- persistent forward LSTM scan -----------------------------------
// 96 blocks x 256 threads; block owns 8 H-columns (32 gate columns).
// Wh slice (768x32) pinned in SMEM; hid double-buffered in global; c in registers.
__global__ void fwd_lstm(const float* __restrict__ Wh,   // [768][3072]
                         const float* __restrict__ xf,   // [S*B][3072] (biases folded)
                         float* __restrict__ hsf)        // [S*B][768]
{
    extern __shared__ float smem_f[];
    float* wh_s  = smem_f;               // 768*32
    float* hid_s = wh_s + 768 * 32;      // 64 kk * 68 (rows padded)
    float* gs    = hid_s + 64 * 68;      // 32 cols * 68 rows

    const int t  = threadIdx.x;
    const int j0 = blockIdx.x * 8;

    // pin Wh slice: column cc = gate*8 + h  ->  global col gate*768 + j0 + h
    for (int idx = t; idx < 768 * 32; idx += 256) {
        int cc = idx & 31, k = idx >> 5;
        int gate = cc >> 3, hh = cc & 7;
        wh_s[idx] = Wh[(size_t)k * 3072 + gate * 768 + j0 + hh];
    }

    const int c0 = 2 * (t & 15);
    const int r0 = 4 * (t >> 4);
    const int h_a = t & 7,          row_a = t >> 3;
    const int h_b = (t + 256) & 7,  row_b = (t + 256) >> 3;
    float creg_a = 0.f, creg_b = 0.f;
    __syncthreads();

    for (int s = 0; s < SS; s++) {
        float acc[4][2] = {};
        if (s > 0) {
            const float* cur = g_hid[s & 1];
            #pragma unroll 1
            for (int ch = 0; ch < 12; ch++) {
                for (int idx = t; idx < 4096; idx += 256) {
                    int kk = idx & 63, row = idx >> 6;
                    hid_s[kk * 68 + row] = cur[row * 768 + ch * 64 + kk];
                }
                __syncthreads();
                const float* whp = wh_s + ch * 64 * 32;
                #pragma unroll 8
                for (int kk = 0; kk < 64; kk++) {
                    float4 hv = *(const float4*)&hid_s[kk * 68 + r0];
                    float2 wv = *(const float2*)&whp[kk * 32 + c0];
                    acc[0][0] += hv.x * wv.x; acc[0][1] += hv.x * wv.y;
                    acc[1][0] += hv.y * wv.x; acc[1][1] += hv.y * wv.y;
                    acc[2][0] += hv.z * wv.x; acc[2][1] += hv.z * wv.y;
                    acc[3][0] += hv.w * wv.x; acc[3][1] += hv.w * wv.y;
                }
                __syncthreads();
            }
        }
        // stash gates to SMEM for per-(row,h) epilogue
        #pragma unroll
        for (int j = 0; j < 2; j++)
            #pragma unroll
            for (int i = 0; i < 4; i++)
                gs[(c0 + j) * 68 + r0 + i] = acc[i][j];
        __syncthreads();

        float* nxt = g_hid[(s + 1) & 1];
        {
            size_t xb = ((size_t)s * 64 + row_a) * 3072 + j0 + h_a;
            float gr = gs[( 0 + h_a) * 68 + row_a] + xf[xb];
            float gf = gs[( 8 + h_a) * 68 + row_a] + xf[xb + 768];
            float gg = gs[(16 + h_a) * 68 + row_a] + xf[xb + 1536];
            float go = gs[(24 + h_a) * 68 + row_a] + xf[xb + 2304];
            float c  = sigmoidf_(gf) * creg_a + sigmoidf_(gr) * tanhf(gg);
            creg_a = c;
            float hv = sigmoidf_(go) * tanhf(c);
            nxt[row_a * 768 + j0 + h_a] = hv;
            hsf[((size_t)s * 64 + row_a) * 768 + j0 + h_a] = hv;
        }
        {
            size_t xb = ((size_t)s * 64 + row_b) * 3072 + j0 + h_b;
            float gr = gs[( 0 + h_b) * 68 + row_b] + xf[xb];
            float gf = gs[( 8 + h_b) * 68 + row_b] + xf[xb + 768];
            float gg = gs[(16 + h_b) * 68 + row_b] + xf[xb + 1536];
            float go = gs[(24 + h_b) * 68 + row_b] + xf[xb + 2304];
            float c  = sigmoidf_(gf) * creg_b + sigmoidf_(gr) * tanhf(gg);
            creg_b = c;
            float hv = sigmoidf_(go) * tanhf(c);
            nxt[row_b * 768 + j0 + h_b] = hv;
            hsf[((size_t)s * 64 + row_b) * 768 + j0 + h_b] = hv;
        }
        grid_bar(gridDim.x);
    }
}

// ---------------- backward direction: 49152 independent reverse scans ------------
__global__ void bwd_scan(const float* __restrict__ xb, const float* __restrict__ hTW,
                         float* __restrict__ hsb)
{
    int tid = blockIdx.x * blockDim.x + threadIdx.x;   // 0..49151
    int h = tid % 768, b = tid / 768;
    float hr = hTW[b * 3072 + h];
    float hf = hTW[b * 3072 + 768 + h];
    float hg = hTW[b * 3072 + 1536 + h];
    float ho = hTW[b * 3072 + 2304 + h];
    float c2 = 0.f;
    for (int s = SS - 1; s >= 0; s--) {
        size_t base = ((size_t)s * 64 + b) * 3072 + h;
        float r = sigmoidf_(xb[base]          + hr);
        float f = sigmoidf_(xb[base + 768]    + hf);
        float g = tanhf    (xb[base + 1536]   + hg);
        float o = sigmoidf_(xb[base + 2304]   + ho);
        c2 = f * c2 + r * g;
        hsb[((size_t)s * 64 + b) * 768 + h] = o * tanhf(c2);
    }
}

// ---------------- output GEMM: [32768,1536(concat)] @ [1536,32] + bout + pad -----
__global__ void out_gemm(const float* __restrict__ hsf, const float* __restrict__ hsb,
                         const float* __restrict__ Wout, const float* __restrict__ bout,
                         const int* __restrict__ tokens, float* __restrict__ out)
{
    __shared__ __align__(16) float As[16][132];
    __shared__ __align__(16) float Bs[16][32];
    const int t  = threadIdx.x;
    const int m0 = blockIdx.y * 128;
    const int c0 = 4 * (t & 7);
    const int r0 = 4 * (t >> 3);
    const int mload = t >> 2;
    const int kq    = (t & 3) * 4;
    float acc[4][4] = {};
    for (int k0 = 0; k0 < 1536; k0 += 16) {
        const float* srcbase = (k0 < 768) ? hsf : hsb;
        int koff = (k0 < 768) ? k0 : (k0 - 768);
        #pragma unroll
        for (int half = 0; half < 2; half++) {
            int m = mload + half * 64;
            float4 v = *(const float4*)(srcbase + (size_t)(m0 + m) * 768 + koff + kq);
            As[kq + 0][m] = v.x; As[kq + 1][m] = v.y;
            As[kq + 2][m] = v.z; As[kq + 3][m] = v.w;
        }
        #pragma unroll
        for (int p = 0; p < 2; p++) {
            int idx = t + p * 256;
            int kk = idx >> 5, n = idx & 31;
            Bs[kk][n] = Wout[(size_t)(k0 + kk) * 32 + n];
        }
        __syncthreads();
        #pragma unroll
        for (int kk = 0; kk < 16; kk++) {
            float4 a = *(const float4*)&As[kk][r0];
            float4 b = *(const float4*)&Bs[kk][c0];
            acc[0][0] += a.x*b.x; acc[0][1] += a.x*b.y; acc[0][2] += a.x*b.z; acc[0][3] += a.x*b.w;
            acc[1][0] += a.y*b.x; acc[1][1] += a.y*b.y; acc[1][2] += a.y*b.z; acc[1][3] += a.y*b.w;
            acc[2][0] += a.z*b.x; acc[2][1] += a.z*b.y; acc[2][2] += a.z*b.z; acc[2][3] += a.z*b.w;
            acc[3][0] += a.w*b.x; acc[3][1] += a.w*b.y; acc[3][2] += a.w*b.z; acc[3][3] += a.w*b.w;
        }
        __syncthreads();
    }
    #pragma unroll
    for (int i = 0; i < 4; i++) {
        int m = m0 + r0 + i;
        float4 v = make_float4(acc[i][0] + bout[c0],     acc[i][1] + bout[c0 + 1],
                               acc[i][2] + bout[c0 + 2], acc[i][3] + bout[c0 + 3]);
        if (c0 == 0 && tokens[m] == 1) v.x += 10000.0f;
        *(float4*)&out[(size_t)m * 32 + c0] = v;
    }
}

// ---------------- launch ----------------------------------------------------------
extern "C" void kernel_launch(void* const* d_in, const int* in_sizes, int n_in,
                              void* d_out, int out_size)
{
    const int*   tokens    = (const int*)  d_in[0];
    // d_in[1] = tags (unused)
    const float* embedding = (const float*)d_in[2];
    const float* Wi_f      = (const float*)d_in[3];
    const float* bi_f      = (const float*)d_in[4];
    const float* Wh_f      = (const float*)d_in[5];
    const float* bh_f      = (const float*)d_in[6];
    const float* Wi_b      = (const float*)d_in[7];
    const float* bi_b      = (const float*)d_in[8];
    const float* Wh_b      = (const float*)d_in[9];
    const float* bh_b      = (const float*)d_in[10];
    const float* Wout      = (const float*)d_in[11];
    const float* bout      = (const float*)d_in[12];
    float* out = (float*)d_out;

    float *xf, *xb, *hsf, *hsb, *hTW;
    cudaGetSymbolAddress((void**)&xf,  g_xf);
    cudaGetSymbolAddress((void**)&xb,  g_xb);
    cudaGetSymbolAddress((void**)&hsf, g_hsf);
    cudaGetSymbolAddress((void**)&hsb, g_hsb);
    cudaGetSymbolAddress((void**)&hTW, g_hTW);

    const int fwd_smem = (768 * 32 + 64 * 68 + 32 * 68) * 4;   // 124416 B
    cudaFuncSetAttribute(fwd_lstm, cudaFuncAttributeMaxDynamicSharedMemorySize, fwd_smem);

    // 1+2: input gate precompute (gathered embedding GEMMs)
    dim3 gA(G4 / 64, SB / 64);
    sgemm64<<<gA, 256>>>(embedding, tokens, Wi_f, SB, G4, EE, bi_f, bh_f, xf);
    sgemm64<<<gA, 256>>>(embedding, tokens, Wi_b, SB, G4, EE, nullptr, nullptr, xb);

    // 3: forward recurrence (persistent)
    fwd_lstm<<<NBLK_FWD, 256, fwd_smem>>>(Wh_f, xf, hsf);

    // 4: hTW = hT @ Wh_b + bi_b + bh_b   (hT = hs_f[last step])
    sgemm64<<<dim3(G4 / 64, 1), 256>>>(hsf + (size_t)(SS - 1) * BB * HH, nullptr, Wh_b,
                                       BB, G4, HH, bi_b, bh_b, hTW);

    // 5: backward direction (independent reverse scans)
    bwd_scan<<<(BB * HH) / 256, 256>>>(xb, hTW, hsb);

    // 6: output projection + pad bias
    out_gemm<<<dim3(1, SB / 128), 256>>>(hsf, hsb, Wout, bout, tokens, out);
}

// round 3
// speedup vs baseline: 1.7223x; 1.7223x over previous
#include <cuda_runtime.h>
#include <cuda_bf16.h>
#include <math.h>
#include <stdint.h>

#define SS   512
#define BB   64
#define EE   512
#define HH   768
#define G4   3072      // 4*H
#define SB   (SS*BB)   // 32768
#define NBLK_FWD 96

// ---------------- scratch (static device globals; allocation-free launch) --------
__device__ float g_xf [SB * G4];
__device__ float g_xb [SB * G4];
__device__ float g_hsf[SB * HH];
__device__ float g_hsb[SB * HH];
__device__ float g_hid[2][BB * HH];
__device__ float g_hTW[BB * G4];
__device__ unsigned g_bar_count;
__device__ unsigned g_bar_gen;

__device__ __forceinline__ float sigmoidf_(float x) { return 1.0f / (1.0f + expf(-x)); }

__device__ __forceinline__ uint32_t smem_u32(const void* p) {
    uint32_t a;
    asm("{ .reg .u64 t; cvta.to.shared.u64 t, %1; cvt.u32.u64 %0, t; }" : "=r"(a) : "l"(p));
    return a;
}

// pack two floats to bf16x2 (e0 -> low half, e1 -> high half), round-to-nearest
__device__ __forceinline__ uint32_t bpack(float e0, float e1) {
    uint32_t r;
    asm("cvt.rn.bf16x2.f32 %0, %1, %2;" : "=r"(r) : "f"(e1), "f"(e0));
    return r;
}

#define LDSM_X4(r0, r1, r2, r3, addr)                                           \
    asm volatile("ldmatrix.sync.aligned.m8n8.x4.shared.b16 {%0,%1,%2,%3}, [%4];" \
                 : "=r"(r0), "=r"(r1), "=r"(r2), "=r"(r3) : "r"(addr))

__device__ __forceinline__ void mma_bf16(float (&d)[4], const uint32_t (&a)[4],
                                         uint32_t b0, uint32_t b1) {
    asm volatile("mma.sync.aligned.m16n8k16.row.col.f32.bf16.bf16.f32 "
                 "{%0,%1,%2,%3}, {%4,%5,%6,%7}, {%8,%9}, {%0,%1,%2,%3};"
                 : "+f"(d[0]), "+f"(d[1]), "+f"(d[2]), "+f"(d[3])
                 : "r"(a[0]), "r"(a[1]), "r"(a[2]), "r"(a[3]), "r"(b0), "r"(b1));
}

// =================== bf16x3 mma.sync GEMM: C[M,3072] = gather(emb)[M,512] @ W + b
// CTA tile 128x128, BK=32, 256 thr (8 warps 4m x 2n, each 32x64), double-buffered.
// smem per buffer: Ahi/Alo/Bhi/Blo, each 128 rows x 80B (K-major, stride 80 ->
// conflict-free ldmatrix). Total 2*40960 + 512(bias) = 82432 B.
#define TSTRIDE 80
#define MAT_SZ  (128 * TSTRIDE)      // 10240
#define BUF_SZ  (4 * MAT_SZ)         // 40960
#define GEMM_SMEM (2 * BUF_SZ + 512)

__global__ void __launch_bounds__(256, 1) mma_gemm(
    const float* __restrict__ emb, const int* __restrict__ tokens,
    const float* __restrict__ W,
    const float* __restrict__ bias1, const float* __restrict__ bias2,
    float* __restrict__ C)
{
    extern __shared__ char sm[];
    const uint32_t sbase = smem_u32(sm);
    const int t  = threadIdx.x;
    const int n0 = blockIdx.x * 128;
    const int m0 = blockIdx.y * 128;
    float* bsum = (float*)(sm + 2 * BUF_SZ);

    if (t < 128) {
        float b = 0.f;
        if (bias1) b = bias1[n0 + t] + bias2[n0 + t];
        bsum[t] = b;
    }

    // ---- staging thread mapping ----
    const int kq = t & 7;            // A: float4 col (k = kq*4)
    const int rb = t >> 3;           // A: row base (+32*i)
    int tok[4];
    #pragma unroll
    for (int i = 0; i < 4; i++) tok[i] = tokens[m0 + rb + 32 * i];
    const int bn  = t & 127;         // B: n row
    const int bkb = (t >> 7) * 16;   // B: k base (+j, j=0..15)

    // ---- prologue: load chunk 0 into registers ----
    float4 av[4]; float bv[16];
    #pragma unroll
    for (int i = 0; i < 4; i++)
        av[i] = *(const float4*)(emb + (size_t)tok[i] * EE + kq * 4);
    #pragma unroll
    for (int j = 0; j < 16; j++)
        bv[j] = W[(size_t)(bkb + j) * G4 + n0 + bn];

    // ---- warp tiling / ldmatrix offsets ----
    const int lane = t & 31, wid = t >> 5;
    const int mbase = (wid & 3) * 32, nbase = (wid >> 2) * 64;
    const int lt = lane >> 3, ll = lane & 7;
    const int dr = (lt & 1) * 8, dk = (lt >> 1) * 8;
    const int a_off = (mbase + dr + ll) * TSTRIDE + dk * 2;   // + mf*1280 + ks*32
    const int b_off = (nbase + dr + ll) * TSTRIDE + dk * 2;   // + j*1280  + ks*32

    float acc[2][8][4];
    #pragma unroll
    for (int a = 0; a < 2; a++)
        #pragma unroll
        for (int b = 0; b < 8; b++)
            #pragma unroll
            for (int c = 0; c < 4; c++) acc[a][b][c] = 0.f;

    for (int ch = 0; ch < 16; ch++) {
        char* buf = sm + (ch & 1) * BUF_SZ;
        // ---- convert + store chunk ch (hi = truncate, lo = residual rn) ----
        #pragma unroll
        for (int i = 0; i < 4; i++) {
            const int row = rb + 32 * i;
            float4 v = av[i];
            uint32_t bx = __float_as_uint(v.x), by = __float_as_uint(v.y);
            uint32_t bz = __float_as_uint(v.z), bw = __float_as_uint(v.w);
            uint32_t hi0 = __byte_perm(bx, by, 0x7632);
            uint32_t hi1 = __byte_perm(bz, bw, 0x7632);
            float lx = v.x - __uint_as_float(bx & 0xFFFF0000u);
            float ly = v.y - __uint_as_float(by & 0xFFFF0000u);
            float lz = v.z - __uint_as_float(bz & 0xFFFF0000u);
            float lw = v.w - __uint_as_float(bw & 0xFFFF0000u);
            *(uint2*)(buf +          row * TSTRIDE + kq * 8) = make_uint2(hi0, hi1);
            *(uint2*)(buf + MAT_SZ + row * TSTRIDE + kq * 8) =
                make_uint2(bpack(lx, ly), bpack(lz, lw));
        }
        #pragma unroll
        for (int jj = 0; jj < 4; jj++) {
            float x0 = bv[4*jj], x1 = bv[4*jj+1], x2 = bv[4*jj+2], x3 = bv[4*jj+3];
            uint32_t b0 = __float_as_uint(x0), b1 = __float_as_uint(x1);
            uint32_t b2 = __float_as_uint(x2), b3 = __float_as_uint(x3);
            uint32_t hi0 = __byte_perm(b0, b1, 0x7632);
            uint32_t hi1 = __byte_perm(b2, b3, 0x7632);
            float l0 = x0 - __uint_as_float(b0 & 0xFFFF0000u);
            float l1 = x1 - __uint_as_float(b1 & 0xFFFF0000u);
            float l2 = x2 - __uint_as_float(b2 & 0xFFFF0000u);
            float l3 = x3 - __uint_as_float(b3 & 0xFFFF0000u);
            int off = bn * TSTRIDE + (bkb + 4*jj) * 2;
            *(uint2*)(buf + 2*MAT_SZ + off) = make_uint2(hi0, hi1);
            *(uint2*)(buf + 3*MAT_SZ + off) = make_uint2(bpack(l0, l1), bpack(l2, l3));
        }
        __syncthreads();

        // ---- prefetch chunk ch+1 ----
        if (ch < 15) {
            const int k0 = (ch + 1) * 32;
            #pragma unroll
            for (int i = 0; i < 4; i++)
                av[i] = *(const float4*)(emb + (size_t)tok[i] * EE + k0 + kq * 4);
            #pragma unroll
            for (int j = 0; j < 16; j++)
                bv[j] = W[(size_t)(k0 + bkb + j) * G4 + n0 + bn];
        }

        // ---- mma on chunk ch ----
        const uint32_t bu  = sbase + (ch & 1) * BUF_SZ;
        const uint32_t Ahi = bu, Alo = bu + MAT_SZ, Bhi = bu + 2*MAT_SZ, Blo = bu + 3*MAT_SZ;
        #pragma unroll
        for (int ks = 0; ks < 2; ks++) {
            uint32_t ah[2][4], al[2][4];
            #pragma unroll
            for (int mf = 0; mf < 2; mf++) {
                LDSM_X4(ah[mf][0], ah[mf][1], ah[mf][2], ah[mf][3],
                        Ahi + a_off + mf * 1280 + ks * 32);
                LDSM_X4(al[mf][0], al[mf][1], al[mf][2], al[mf][3],
                        Alo + a_off + mf * 1280 + ks * 32);
            }
            #pragma unroll
            for (int j = 0; j < 4; j++) {
                uint32_t bh[4], bl[4];
                LDSM_X4(bh[0], bh[1], bh[2], bh[3], Bhi + b_off + j * 1280 + ks * 32);
                LDSM_X4(bl[0], bl[1], bl[2], bl[3], Blo + b_off + j * 1280 + ks * 32);
                #pragma unroll
                for (int mf = 0; mf < 2; mf++) {
                    // n-frag 0: regs {r0 (n+0,k0..7), r2 (n+0,k8..15)}
                    mma_bf16(acc[mf][2*j],   ah[mf], bh[0], bh[2]);
                    mma_bf16(acc[mf][2*j],   ah[mf], bl[0], bl[2]);
                    mma_bf16(acc[mf][2*j],   al[mf], bh[0], bh[2]);
                    // n-frag 1: regs {r1 (n+8,k0..7), r3 (n+8,k8..15)}
                    mma_bf16(acc[mf][2*j+1], ah[mf], bh[1], bh[3]);
                    mma_bf16(acc[mf][2*j+1], ah[mf], bl[1], bl[3]);
                    mma_bf16(acc[mf][2*j+1], al[mf], bh[1], bh[3]);
                }
            }
        }
    }

    // ---- epilogue ----
    const int g = lane >> 2, tg = (lane & 3) * 2;
    #pragma unroll
    for (int mf = 0; mf < 2; mf++) {
        #pragma unroll
        for (int jj = 0; jj < 8; jj++) {
            const int nloc = nbase + jj * 8 + tg;
            const float b0 = bsum[nloc], b1 = bsum[nloc + 1];
            const int r0 = m0 + mbase + mf * 16 + g;
            const size_t col = (size_t)(n0 + nloc);
            *(float2*)(C + (size_t)r0 * G4 + col) =
                make_float2(acc[mf][jj][0] + b0, acc[mf][jj][1] + b1);
            *(float2*)(C + (size_t)(r0 + 8) * G4 + col) =
                make_float2(acc[mf][jj][2] + b0, acc[mf][jj][3] + b1);
        }
    }
}

// ---------------- software grid barrier (persistent kernel) ----------------------
__device__ __forceinline__ void grid_bar(unsigned nblocks) {
    __threadfence();
    __syncthreads();
    if (threadIdx.x == 0) {
        unsigned gen = *(volatile unsigned*)&g_bar_gen;
        if (atomicAdd(&g_bar_count, 1u) == nblocks - 1u) {
            atomicExch(&g_bar_count, 0u);
            __threadfence();
            *(volatile unsigned*)&g_bar_gen = gen + 1u;
        } else {
            while (*(volatile unsigned*)&g_bar_gen == gen) { __nanosleep(64); }
        }
        __threadfence();
    }
    __syncthreads();
}

// ---------------- small fp32 GEMM (kept for hTW only) ----------------------------
__global__ void sgemm64(const float* __restrict__ A, const int* __restrict__ gather,
                        const float* __restrict__ W, int M, int N, int K,
                        const float* __restrict__ bias1, const float* __restrict__ bias2,
                        float* __restrict__ C)
{
    __shared__ __align__(16) float As[16][68];
    __shared__ __align__(16) float Bs[16][64];
    const int t  = threadIdx.x;
    const int m0 = blockIdx.y * 64;
    const int n0 = blockIdx.x * 64;
    const int c0 = 4 * (t & 15);
    const int r0 = 4 * (t >> 4);
    const int mload = t >> 2;
    const int kq    = (t & 3) * 4;
    const int nload = t & 63;
    const int kload = t >> 6;

    const float* arow;
    {
        int mg = m0 + mload;
        arow = gather ? (A + (size_t)gather[mg] * K) : (A + (size_t)mg * K);
    }

    float acc[4][4] = {};
    for (int k0 = 0; k0 < K; k0 += 16) {
        float4 a4 = *(const float4*)(arow + k0 + kq);
        As[kq + 0][mload] = a4.x; As[kq + 1][mload] = a4.y;
        As[kq + 2][mload] = a4.z; As[kq + 3][mload] = a4.w;
        #pragma unroll
        for (int p = 0; p < 4; p++) {
            int kk = kload + p * 4;
            Bs[kk][nload] = W[(size_t)(k0 + kk) * N + n0 + nload];
        }
        __syncthreads();
        #pragma unroll
        for (int kk = 0; kk < 16; kk++) {
            float4 a = *(const float4*)&As[kk][r0];
            float4 b = *(const float4*)&Bs[kk][c0];
            acc[0][0] += a.x*b.x; acc[0][1] += a.x*b.y; acc[0][2] += a.x*b.z; acc[0][3] += a.x*b.w;
            acc[1][0] += a.y*b.x; acc[1][1] += a.y*b.y; acc[1][2] += a.y*b.z; acc[1][3] += a.y*b.w;
            acc[2][0] += a.z*b.x; acc[2][1] += a.z*b.y; acc[2][2] += a.z*b.z; acc[2][3] += a.z*b.w;
            acc[3][0] += a.w*b.x; acc[3][1] += a.w*b.y; acc[3][2] += a.w*b.z; acc[3][3] += a.w*b.w;
        }
        __syncthreads();
    }
    float badd[4];
    #pragma unroll
    for (int j = 0; j < 4; j++) {
        float b = 0.f;
        if (bias1) b += bias1[n0 + c0 + j];
        if (bias2) b += bias2[n0 + c0 + j];
        badd[j] = b;
    }
    #pragma unroll
    for (int i = 0; i < 4; i++) {
        float4 v = make_float4(acc[i][0] + badd[0], acc[i][1] + badd[1],
                               acc[i][2] + badd[2], acc[i][3] + badd[3]);
        *(float4*)&C[(size_t)(m0 + r0 + i) * N + n0 + c0] = v;
    }
}

// ---------------- persistent forward LSTM scan -----------------------------------
__global__ void fwd_lstm(const float* __restrict__ Wh,
                         const float* __restrict__ xf,
                         float* __restrict__ hsf)
{
    extern __shared__ float smem_f[];
    float* wh_s  = smem_f;
    float* hid_s = wh_s + 768 * 32;
    float* gs    = hid_s + 64 * 68;

    const int t  = threadIdx.x;
    const int j0 = blockIdx.x * 8;

    for (int idx = t; idx < 768 * 32; idx += 256) {
        int cc = idx & 31, k = idx >> 5;
        int gate = cc >> 3, hh = cc & 7;
        wh_s[idx] = Wh[(size_t)k * 3072 + gate * 768 + j0 + hh];
    }

    const int c0 = 2 * (t & 15);
    const int r0 = 4 * (t >> 4);
    const int h_a = t & 7,          row_a = t >> 3;
    const int h_b = (t + 256) & 7,  row_b = (t + 256) >> 3;
    float creg_a = 0.f, creg_b = 0.f;
    __syncthreads();

    for (int s = 0; s < SS; s++) {
        float acc[4][2] = {};
        if (s > 0) {
            const float* cur = g_hid[s & 1];
            #pragma unroll 1
            for (int ch = 0; ch < 12; ch++) {
                for (int idx = t; idx < 4096; idx += 256) {
                    int kk = idx & 63, row = idx >> 6;
                    hid_s[kk * 68 + row] = cur[row * 768 + ch * 64 + kk];
                }
                __syncthreads();
                const float* whp = wh_s + ch * 64 * 32;
                #pragma unroll 8
                for (int kk = 0; kk < 64; kk++) {
                    float4 hv = *(const float4*)&hid_s[kk * 68 + r0];
                    float2 wv = *(const float2*)&whp[kk * 32 + c0];
                    acc[0][0] += hv.x * wv.x; acc[0][1] += hv.x * wv.y;
                    acc[1][0] += hv.y * wv.x; acc[1][1] += hv.y * wv.y;
                    acc[2][0] += hv.z * wv.x; acc[2][1] += hv.z * wv.y;
                    acc[3][0] += hv.w * wv.x; acc[3][1] += hv.w * wv.y;
                }
                __syncthreads();
            }
        }
        #pragma unroll
        for (int j = 0; j < 2; j++)
            #pragma unroll
            for (int i = 0; i < 4; i++)
                gs[(c0 + j) * 68 + r0 + i] = acc[i][j];
        __syncthreads();

        float* nxt = g_hid[(s + 1) & 1];
        {
            size_t xb = ((size_t)s * 64 + row_a) * 3072 + j0 + h_a;
            float gr = gs[( 0 + h_a) * 68 + row_a] + xf[xb];
            float gf = gs[( 8 + h_a) * 68 + row_a] + xf[xb + 768];
            float gg = gs[(16 + h_a) * 68 + row_a] + xf[xb + 1536];
            float go = gs[(24 + h_a) * 68 + row_a] + xf[xb + 2304];
            float c  = sigmoidf_(gf) * creg_a + sigmoidf_(gr) * tanhf(gg);
            creg_a = c;
            float hv = sigmoidf_(go) * tanhf(c);
            nxt[row_a * 768 + j0 + h_a] = hv;
            hsf[((size_t)s * 64 + row_a) * 768 + j0 + h_a] = hv;
        }
        {
            size_t xb = ((size_t)s * 64 + row_b) * 3072 + j0 + h_b;
            float gr = gs[( 0 + h_b) * 68 + row_b] + xf[xb];
            float gf = gs[( 8 + h_b) * 68 + row_b] + xf[xb + 768];
            float gg = gs[(16 + h_b) * 68 + row_b] + xf[xb + 1536];
            float go = gs[(24 + h_b) * 68 + row_b] + xf[xb + 2304];
            float c  = sigmoidf_(gf) * creg_b + sigmoidf_(gr) * tanhf(gg);
            creg_b = c;
            float hv = sigmoidf_(go) * tanhf(c);
            nxt[row_b * 768 + j0 + h_b] = hv;
            hsf[((size_t)s * 64 + row_b) * 768 + j0 + h_b] = hv;
        }
        grid_bar(gridDim.x);
    }
}

// ---------------- backward direction ---------------------------------------------
__global__ void bwd_scan(const float* __restrict__ xb, const float* __restrict__ hTW,
                         float* __restrict__ hsb)
{
    int tid = blockIdx.x * blockDim.x + threadIdx.x;
    int h = tid % 768, b = tid / 768;
    float hr = hTW[b * 3072 + h];
    float hf = hTW[b * 3072 + 768 + h];
    float hg = hTW[b * 3072 + 1536 + h];
    float ho = hTW[b * 3072 + 2304 + h];
    float c2 = 0.f;
    for (int s = SS - 1; s >= 0; s--) {
        size_t base = ((size_t)s * 64 + b) * 3072 + h;
        float r = sigmoidf_(xb[base]          + hr);
        float f = sigmoidf_(xb[base + 768]    + hf);
        float g = tanhf    (xb[base + 1536]   + hg);
        float o = sigmoidf_(xb[base + 2304]   + ho);
        c2 = f * c2 + r * g;
        hsb[((size_t)s * 64 + b) * 768 + h] = o * tanhf(c2);
    }
}

// ---------------- output GEMM -----------------------------------------------------
__global__ void out_gemm(const float* __restrict__ hsf, const float* __restrict__ hsb,
                         const float* __restrict__ Wout, const float* __restrict__ bout,
                         const int* __restrict__ tokens, float* __restrict__ out)
{
    __shared__ __align__(16) float As[16][132];
    __shared__ __align__(16) float Bs[16][32];
    const int t  = threadIdx.x;
    const int m0 = blockIdx.y * 128;
    const int c0 = 4 * (t & 7);
    const int r0 = 4 * (t >> 3);
    const int mload = t >> 2;
    const int kq    = (t & 3) * 4;
    float acc[4][4] = {};
    for (int k0 = 0; k0 < 1536; k0 += 16) {
        const float* srcbase = (k0 < 768) ? hsf : hsb;
        int koff = (k0 < 768) ? k0 : (k0 - 768);
        #pragma unroll
        for (int half = 0; half < 2; half++) {
            int m = mload + half * 64;
            float4 v = *(const float4*)(srcbase + (size_t)(m0 + m) * 768 + koff + kq);
            As[kq + 0][m] = v.x; As[kq + 1][m] = v.y;
            As[kq + 2][m] = v.z; As[kq + 3][m] = v.w;
        }
        #pragma unroll
        for (int p = 0; p < 2; p++) {
            int idx = t + p * 256;
            int kk = idx >> 5, n = idx & 31;
            Bs[kk][n] = Wout[(size_t)(k0 + kk) * 32 + n];
        }
        __syncthreads();
        #pragma unroll
        for (int kk = 0; kk < 16; kk++) {
            float4 a = *(const float4*)&As[kk][r0];
            float4 b = *(const float4*)&Bs[kk][c0];
            acc[0][0] += a.x*b.x; acc[0][1] += a.x*b.y; acc[0][2] += a.x*b.z; acc[0][3] += a.x*b.w;
            acc[1][0] += a.y*b.x; acc[1][1] += a.y*b.y; acc[1][2] += a.y*b.z; acc[1][3] += a.y*b.w;
            acc[2][0] += a.z*b.x; acc[2][1] += a.z*b.y; acc[2][2] += a.z*b.z; acc[2][3] += a.z*b.w;
            acc[3][0] += a.w*b.x; acc[3][1] += a.w*b.y; acc[3][2] += a.w*b.z; acc[3][3] += a.w*b.w;
        }
        __syncthreads();
    }
    #pragma unroll
    for (int i = 0; i < 4; i++) {
        int m = m0 + r0 + i;
        float4 v = make_float4(acc[i][0] + bout[c0],     acc[i][1] + bout[c0 + 1],
                               acc[i][2] + bout[c0 + 2], acc[i][3] + bout[c0 + 3]);
        if (c0 == 0 && tokens[m] == 1) v.x += 10000.0f;
        *(float4*)&out[(size_t)m * 32 + c0] = v;
    }
}

// ---------------- launch ----------------------------------------------------------
extern "C" void kernel_launch(void* const* d_in, const int* in_sizes, int n_in,
                              void* d_out, int out_size)
{
    const int*   tokens    = (const int*)  d_in[0];
    const float* embedding = (const float*)d_in[2];
    const float* Wi_f      = (const float*)d_in[3];
    const float* bi_f      = (const float*)d_in[4];
    const float* Wh_f      = (const float*)d_in[5];
    const float* bh_f      = (const float*)d_in[6];
    const float* Wi_b      = (const float*)d_in[7];
    const float* bi_b      = (const float*)d_in[8];
    const float* Wh_b      = (const float*)d_in[9];
    const float* bh_b      = (const float*)d_in[10];
    const float* Wout      = (const float*)d_in[11];
    const float* bout      = (const float*)d_in[12];
    float* out = (float*)d_out;

    float *xf, *xb, *hsf, *hsb, *hTW;
    cudaGetSymbolAddress((void**)&xf,  g_xf);
    cudaGetSymbolAddress((void**)&xb,  g_xb);
    cudaGetSymbolAddress((void**)&hsf, g_hsf);
    cudaGetSymbolAddress((void**)&hsb, g_hsb);
    cudaGetSymbolAddress((void**)&hTW, g_hTW);

    const int fwd_smem = (768 * 32 + 64 * 68 + 32 * 68) * 4;
    cudaFuncSetAttribute(fwd_lstm, cudaFuncAttributeMaxDynamicSharedMemorySize, fwd_smem);
    cudaFuncSetAttribute(mma_gemm, cudaFuncAttributeMaxDynamicSharedMemorySize, GEMM_SMEM);

    // 1+2: input gate precompute on tensor cores (bf16x3 mma.sync)
    dim3 gG(G4 / 128, SB / 128);
    mma_gemm<<<gG, 256, GEMM_SMEM>>>(embedding, tokens, Wi_f, bi_f, bh_f, xf);
    mma_gemm<<<gG, 256, GEMM_SMEM>>>(embedding, tokens, Wi_b, nullptr, nullptr, xb);

    // 3: forward recurrence (persistent)
    fwd_lstm<<<NBLK_FWD, 256, fwd_smem>>>(Wh_f, xf, hsf);

    // 4: hTW = hT @ Wh_b + bi_b + bh_b
    sgemm64<<<dim3(G4 / 64, 1), 256>>>(hsf + (size_t)(SS - 1) * BB * HH, nullptr, Wh_b,
                                       BB, G4, HH, bi_b, bh_b, hTW);

    // 5: backward direction
    bwd_scan<<<(BB * HH) / 256, 256>>>(xb, hTW, hsb);

    // 6: output projection + pad bias
    out_gemm<<<dim3(1, SB / 128), 256>>>(hsf, hsb, Wout, bout, tokens, out);
}

// round 4
// speedup vs baseline: 4.5691x; 2.6529x over previous
#include <cuda_runtime.h>
#include <cuda_bf16.h>
#include <math.h>
#include <stdint.h>

#define SS   512
#define BB   64
#define EE   512
#define HH   768
#define G4   3072      // 4*H
#define SB   (SS*BB)   // 32768
#define NBLK_FWD 96

// ---------------- scratch (static device globals; allocation-free launch) --------
__device__ float g_xf [SB * G4];
__device__ float g_xb [SB * G4];
__device__ float g_hsf[SB * HH];
__device__ float g_hsb[SB * HH];
__device__ float g_hTW[BB * G4];
__device__ uint16_t g_hid_hi[2][BB * HH];   // bf16 bits, row-major [row][768]
__device__ uint16_t g_hid_lo[2][BB * HH];
__device__ unsigned g_bar_count;
__device__ unsigned g_bar_gen;

__device__ __forceinline__ float sigmoidf_(float x) { return 1.0f / (1.0f + expf(-x)); }

__device__ __forceinline__ uint32_t smem_u32(const void* p) {
    uint32_t a;
    asm("{ .reg .u64 t; cvta.to.shared.u64 t, %1; cvt.u32.u64 %0, t; }" : "=r"(a) : "l"(p));
    return a;
}

// pack two floats to bf16x2 (e0 -> low half, e1 -> high half), round-to-nearest
__device__ __forceinline__ uint32_t bpack(float e0, float e1) {
    uint32_t r;
    asm("cvt.rn.bf16x2.f32 %0, %1, %2;" : "=r"(r) : "f"(e1), "f"(e0));
    return r;
}
__device__ __forceinline__ uint16_t bf16rn(float x) {
    __nv_bfloat16 h = __float2bfloat16(x);
    return *(uint16_t*)&h;
}

#define LDSM_X4(r0, r1, r2, r3, addr)                                           \
    asm volatile("ldmatrix.sync.aligned.m8n8.x4.shared.b16 {%0,%1,%2,%3}, [%4];" \
                 : "=r"(r0), "=r"(r1), "=r"(r2), "=r"(r3) : "r"(addr))

__device__ __forceinline__ void mma_bf16(float (&d)[4], const uint32_t (&a)[4],
                                         uint32_t b0, uint32_t b1) {
    asm volatile("mma.sync.aligned.m16n8k16.row.col.f32.bf16.bf16.f32 "
                 "{%0,%1,%2,%3}, {%4,%5,%6,%7}, {%8,%9}, {%0,%1,%2,%3};"
                 : "+f"(d[0]), "+f"(d[1]), "+f"(d[2]), "+f"(d[3])
                 : "r"(a[0]), "r"(a[1]), "r"(a[2]), "r"(a[3]), "r"(b0), "r"(b1));
}

// =================== bf16x3 mma.sync GEMM: C[M,3072] = gather(emb)[M,512] @ W + b
#define TSTRIDE 80
#define MAT_SZ  (128 * TSTRIDE)
#define BUF_SZ  (4 * MAT_SZ)
#define GEMM_SMEM (2 * BUF_SZ + 512)

__global__ void __launch_bounds__(256, 1) mma_gemm(
    const float* __restrict__ emb, const int* __restrict__ tokens,
    const float* __restrict__ W,
    const float* __restrict__ bias1, const float* __restrict__ bias2,
    float* __restrict__ C)
{
    extern __shared__ char sm[];
    const uint32_t sbase = smem_u32(sm);
    const int t  = threadIdx.x;
    const int n0 = blockIdx.x * 128;
    const int m0 = blockIdx.y * 128;
    float* bsum = (float*)(sm + 2 * BUF_SZ);

    if (t < 128) {
        float b = 0.f;
        if (bias1) b = bias1[n0 + t] + bias2[n0 + t];
        bsum[t] = b;
    }

    const int kq = t & 7;
    const int rb = t >> 3;
    int tok[4];
    #pragma unroll
    for (int i = 0; i < 4; i++) tok[i] = tokens[m0 + rb + 32 * i];
    const int bn  = t & 127;
    const int bkb = (t >> 7) * 16;

    float4 av[4]; float bv[16];
    #pragma unroll
    for (int i = 0; i < 4; i++)
        av[i] = *(const float4*)(emb + (size_t)tok[i] * EE + kq * 4);
    #pragma unroll
    for (int j = 0; j < 16; j++)
        bv[j] = W[(size_t)(bkb + j) * G4 + n0 + bn];

    const int lane = t & 31, wid = t >> 5;
    const int mbase = (wid & 3) * 32, nbase = (wid >> 2) * 64;
    const int lt = lane >> 3, ll = lane & 7;
    const int dr = (lt & 1) * 8, dk = (lt >> 1) * 8;
    const int a_off = (mbase + dr + ll) * TSTRIDE + dk * 2;
    const int b_off = (nbase + dr + ll) * TSTRIDE + dk * 2;

    float acc[2][8][4];
    #pragma unroll
    for (int a = 0; a < 2; a++)
        #pragma unroll
        for (int b = 0; b < 8; b++)
            #pragma unroll
            for (int c = 0; c < 4; c++) acc[a][b][c] = 0.f;

    for (int ch = 0; ch < 16; ch++) {
        char* buf = sm + (ch & 1) * BUF_SZ;
        #pragma unroll
        for (int i = 0; i < 4; i++) {
            const int row = rb + 32 * i;
            float4 v = av[i];
            uint32_t bx = __float_as_uint(v.x), by = __float_as_uint(v.y);
            uint32_t bz = __float_as_uint(v.z), bw = __float_as_uint(v.w);
            uint32_t hi0 = __byte_perm(bx, by, 0x7632);
            uint32_t hi1 = __byte_perm(bz, bw, 0x7632);
            float lx = v.x - __uint_as_float(bx & 0xFFFF0000u);
            float ly = v.y - __uint_as_float(by & 0xFFFF0000u);
            float lz = v.z - __uint_as_float(bz & 0xFFFF0000u);
            float lw = v.w - __uint_as_float(bw & 0xFFFF0000u);
            *(uint2*)(buf +          row * TSTRIDE + kq * 8) = make_uint2(hi0, hi1);
            *(uint2*)(buf + MAT_SZ + row * TSTRIDE + kq * 8) =
                make_uint2(bpack(lx, ly), bpack(lz, lw));
        }
        #pragma unroll
        for (int jj = 0; jj < 4; jj++) {
            float x0 = bv[4*jj], x1 = bv[4*jj+1], x2 = bv[4*jj+2], x3 = bv[4*jj+3];
            uint32_t b0 = __float_as_uint(x0), b1 = __float_as_uint(x1);
            uint32_t b2 = __float_as_uint(x2), b3 = __float_as_uint(x3);
            uint32_t hi0 = __byte_perm(b0, b1, 0x7632);
            uint32_t hi1 = __byte_perm(b2, b3, 0x7632);
            float l0 = x0 - __uint_as_float(b0 & 0xFFFF0000u);
            float l1 = x1 - __uint_as_float(b1 & 0xFFFF0000u);
            float l2 = x2 - __uint_as_float(b2 & 0xFFFF0000u);
            float l3 = x3 - __uint_as_float(b3 & 0xFFFF0000u);
            int off = bn * TSTRIDE + (bkb + 4*jj) * 2;
            *(uint2*)(buf + 2*MAT_SZ + off) = make_uint2(hi0, hi1);
            *(uint2*)(buf + 3*MAT_SZ + off) = make_uint2(bpack(l0, l1), bpack(l2, l3));
        }
        __syncthreads();

        if (ch < 15) {
            const int k0 = (ch + 1) * 32;
            #pragma unroll
            for (int i = 0; i < 4; i++)
                av[i] = *(const float4*)(emb + (size_t)tok[i] * EE + k0 + kq * 4);
            #pragma unroll
            for (int j = 0; j < 16; j++)
                bv[j] = W[(size_t)(k0 + bkb + j) * G4 + n0 + bn];
        }

        const uint32_t bu  = sbase + (ch & 1) * BUF_SZ;
        const uint32_t Ahi = bu, Alo = bu + MAT_SZ, Bhi = bu + 2*MAT_SZ, Blo = bu + 3*MAT_SZ;
        #pragma unroll
        for (int ks = 0; ks < 2; ks++) {
            uint32_t ah[2][4], al[2][4];
            #pragma unroll
            for (int mf = 0; mf < 2; mf++) {
                LDSM_X4(ah[mf][0], ah[mf][1], ah[mf][2], ah[mf][3],
                        Ahi + a_off + mf * 1280 + ks * 32);
                LDSM_X4(al[mf][0], al[mf][1], al[mf][2], al[mf][3],
                        Alo + a_off + mf * 1280 + ks * 32);
            }
            #pragma unroll
            for (int j = 0; j < 4; j++) {
                uint32_t bh[4], bl[4];
                LDSM_X4(bh[0], bh[1], bh[2], bh[3], Bhi + b_off + j * 1280 + ks * 32);
                LDSM_X4(bl[0], bl[1], bl[2], bl[3], Blo + b_off + j * 1280 + ks * 32);
                #pragma unroll
                for (int mf = 0; mf < 2; mf++) {
                    mma_bf16(acc[mf][2*j],   ah[mf], bh[0], bh[2]);
                    mma_bf16(acc[mf][2*j],   ah[mf], bl[0], bl[2]);
                    mma_bf16(acc[mf][2*j],   al[mf], bh[0], bh[2]);
                    mma_bf16(acc[mf][2*j+1], ah[mf], bh[1], bh[3]);
                    mma_bf16(acc[mf][2*j+1], ah[mf], bl[1], bl[3]);
                    mma_bf16(acc[mf][2*j+1], al[mf], bh[1], bh[3]);
                }
            }
        }
    }

    const int g = lane >> 2, tg = (lane & 3) * 2;
    #pragma unroll
    for (int mf = 0; mf < 2; mf++) {
        #pragma unroll
        for (int jj = 0; jj < 8; jj++) {
            const int nloc = nbase + jj * 8 + tg;
            const float b0 = bsum[nloc], b1 = bsum[nloc + 1];
            const int r0 = m0 + mbase + mf * 16 + g;
            const size_t col = (size_t)(n0 + nloc);
            *(float2*)(C + (size_t)r0 * G4 + col) =
                make_float2(acc[mf][jj][0] + b0, acc[mf][jj][1] + b1);
            *(float2*)(C + (size_t)(r0 + 8) * G4 + col) =
                make_float2(acc[mf][jj][2] + b0, acc[mf][jj][3] + b1);
        }
    }
}

// ---------------- software grid barrier (persistent kernel) ----------------------
__device__ __forceinline__ void grid_bar(unsigned nblocks) {
    __threadfence();
    __syncthreads();
    if (threadIdx.x == 0) {
        unsigned gen = *(volatile unsigned*)&g_bar_gen;
        if (atomicAdd(&g_bar_count, 1u) == nblocks - 1u) {
            atomicExch(&g_bar_count, 0u);
            __threadfence();
            *(volatile unsigned*)&g_bar_gen = gen + 1u;
        } else {
            while (*(volatile unsigned*)&g_bar_gen == gen) { __nanosleep(64); }
        }
        __threadfence();
    }
    __syncthreads();
}

// ---------------- small fp32 GEMM (kept for hTW only) ----------------------------
__global__ void sgemm64(const float* __restrict__ A, const int* __restrict__ gather,
                        const float* __restrict__ W, int M, int N, int K,
                        const float* __restrict__ bias1, const float* __restrict__ bias2,
                        float* __restrict__ C)
{
    __shared__ __align__(16) float As[16][68];
    __shared__ __align__(16) float Bs[16][64];
    const int t  = threadIdx.x;
    const int m0 = blockIdx.y * 64;
    const int n0 = blockIdx.x * 64;
    const int c0 = 4 * (t & 15);
    const int r0 = 4 * (t >> 4);
    const int mload = t >> 2;
    const int kq    = (t & 3) * 4;
    const int nload = t & 63;
    const int kload = t >> 6;

    const float* arow;
    {
        int mg = m0 + mload;
        arow = gather ? (A + (size_t)gather[mg] * K) : (A + (size_t)mg * K);
    }

    float acc[4][4] = {};
    for (int k0 = 0; k0 < K; k0 += 16) {
        float4 a4 = *(const float4*)(arow + k0 + kq);
        As[kq + 0][mload] = a4.x; As[kq + 1][mload] = a4.y;
        As[kq + 2][mload] = a4.z; As[kq + 3][mload] = a4.w;
        #pragma unroll
        for (int p = 0; p < 4; p++) {
            int kk = kload + p * 4;
            Bs[kk][nload] = W[(size_t)(k0 + kk) * N + n0 + nload];
        }
        __syncthreads();
        #pragma unroll
        for (int kk = 0; kk < 16; kk++) {
            float4 a = *(const float4*)&As[kk][r0];
            float4 b = *(const float4*)&Bs[kk][c0];
            acc[0][0] += a.x*b.x; acc[0][1] += a.x*b.y; acc[0][2] += a.x*b.z; acc[0][3] += a.x*b.w;
            acc[1][0] += a.y*b.x; acc[1][1] += a.y*b.y; acc[1][2] += a.y*b.z; acc[1][3] += a.y*b.w;
            acc[2][0] += a.z*b.x; acc[2][1] += a.z*b.y; acc[2][2] += a.z*b.z; acc[2][3] += a.z*b.w;
            acc[3][0] += a.w*b.x; acc[3][1] += a.w*b.y; acc[3][2] += a.w*b.z; acc[3][3] += a.w*b.w;
        }
        __syncthreads();
    }
    float badd[4];
    #pragma unroll
    for (int j = 0; j < 4; j++) {
        float b = 0.f;
        if (bias1) b += bias1[n0 + c0 + j];
        if (bias2) b += bias2[n0 + c0 + j];
        badd[j] = b;
    }
    #pragma unroll
    for (int i = 0; i < 4; i++) {
        float4 v = make_float4(acc[i][0] + badd[0], acc[i][1] + badd[1],
                               acc[i][2] + badd[2], acc[i][3] + badd[3]);
        *(float4*)&C[(size_t)(m0 + r0 + i) * N + n0 + c0] = v;
    }
}

// ---------------- persistent forward LSTM scan, recurrence on tensor cores -------
// 96 blocks x 256 threads; block owns 8 H-cols (32 gate cols).
// Wh slice bf16 hi/lo pinned in smem (n-major, stride 1552B, ldmatrix-clean).
// hid published as bf16 hi/lo in global, streamed per step in 12 chunks of 64x64
// (smem stride 144B), double-buffered, register-prefetched. bf16x3 mma.
#define WSTRIDE 1552
#define HSTRIDE 144
#define FW_WH_HI 0
#define FW_WH_LO 49664
#define FW_HID   99328                 // [db][hi/lo] 4 x 9216
#define FW_GS    136192                // 32 cols x 68 fp32
#define FW_SMEM  144896

__global__ void __launch_bounds__(256, 1) fwd_lstm_mma(
    const float* __restrict__ Wh,      // [768][3072]
    const float* __restrict__ xf,      // [S*B][3072] (biases folded)
    float* __restrict__ hsf)           // [S*B][768]
{
    extern __shared__ char sm[];
    const uint32_t sbase = smem_u32(sm);
    float* gs = (float*)(sm + FW_GS);
    const int t  = threadIdx.x;
    const int j0 = blockIdx.x * 8;

    // ---- stage Wh slice as bf16 hi/lo, n-major [32][768] ----
    for (int idx = t; idx < 768 * 32; idx += 256) {
        int n = idx & 31, k = idx >> 5;
        float v = Wh[(size_t)k * 3072 + (n >> 3) * 768 + j0 + (n & 7)];
        uint32_t b = __float_as_uint(v);
        *(uint16_t*)(sm + FW_WH_HI + n * WSTRIDE + k * 2) = (uint16_t)(b >> 16);
        *(uint16_t*)(sm + FW_WH_LO + n * WSTRIDE + k * 2) =
            bf16rn(v - __uint_as_float(b & 0xFFFF0000u));
    }

    // ---- ldmatrix / mma thread mapping ----
    const int lane = t & 31, wid = t >> 5;
    const int wm = wid & 3, wn = wid >> 2;       // warp tile: m16 x n16
    const int lt = lane >> 3, ll = lane & 7;
    const int dr = (lt & 1) * 8, dk16 = (lt >> 1) * 16;
    const uint32_t a_off = (uint32_t)((wm * 16 + dr + ll) * HSTRIDE + dk16);
    const uint32_t b_hiA = sbase + FW_WH_HI + (wn * 16 + dr + ll) * WSTRIDE + dk16;
    const uint32_t b_loA = sbase + FW_WH_LO + (wn * 16 + dr + ll) * WSTRIDE + dk16;

    // hid chunk staging mapping (2 uint4 per buffer per thread)
    const int r0r = t >> 3,           sg0 = t & 7;
    const int r1r = (t + 256) >> 3,   sg1 = t & 7;    // (t+256)&7 == t&7
    const size_t ga0 = (size_t)(r0r * 768 + sg0 * 8) * 2;
    const size_t ga1 = (size_t)(r1r * 768 + sg1 * 8) * 2;
    const uint32_t sa0 = r0r * HSTRIDE + sg0 * 16;
    const uint32_t sa1 = r1r * HSTRIDE + sg1 * 16;

    // epilogue mapping (2 (row,h) pairs per thread)
    const int h_a = t & 7, row_a = t >> 3;
    const int h_b = h_a,   row_b = 32 + (t >> 3);
    float creg_a = 0.f, creg_b = 0.f;
    __syncthreads();

    for (int s = 0; s < SS; s++) {
        // prefetch xf for this step (latency hidden under mma chunks)
        float xfa[4], xfb[4];
        {
            size_t ba = ((size_t)s * 64 + row_a) * 3072 + j0 + h_a;
            size_t bb = ((size_t)s * 64 + row_b) * 3072 + j0 + h_b;
            #pragma unroll
            for (int g = 0; g < 4; g++) { xfa[g] = xf[ba + g * 768]; xfb[g] = xf[bb + g * 768]; }
        }
        float acc[2][4] = {};
        if (s > 0) {
            const char* chi = (const char*)g_hid_hi[s & 1];
            const char* clo = (const char*)g_hid_lo[s & 1];
            uint4 rh0 = *(const uint4*)(chi + ga0);
            uint4 rh1 = *(const uint4*)(chi + ga1);
            uint4 rl0 = *(const uint4*)(clo + ga0);
            uint4 rl1 = *(const uint4*)(clo + ga1);
            #pragma unroll 1
            for (int ch = 0; ch < 12; ch++) {
                char* buf = sm + FW_HID + (ch & 1) * 18432;
                *(uint4*)(buf + sa0)        = rh0;
                *(uint4*)(buf + sa1)        = rh1;
                *(uint4*)(buf + 9216 + sa0) = rl0;
                *(uint4*)(buf + 9216 + sa1) = rl1;
                __syncthreads();
                if (ch < 11) {
                    size_t off = (size_t)(ch + 1) * 128;
                    rh0 = *(const uint4*)(chi + ga0 + off);
                    rh1 = *(const uint4*)(chi + ga1 + off);
                    rl0 = *(const uint4*)(clo + ga0 + off);
                    rl1 = *(const uint4*)(clo + ga1 + off);
                }
                const uint32_t Ah  = sbase + FW_HID + (ch & 1) * 18432 + a_off;
                const uint32_t Al  = Ah + 9216;
                const uint32_t wko = (uint32_t)ch * 128;
                #pragma unroll
                for (int kf = 0; kf < 4; kf++) {
                    uint32_t ah[4], al[4], bh[4], bl[4];
                    LDSM_X4(ah[0], ah[1], ah[2], ah[3], Ah + kf * 32);
                    LDSM_X4(al[0], al[1], al[2], al[3], Al + kf * 32);
                    LDSM_X4(bh[0], bh[1], bh[2], bh[3], b_hiA + wko + kf * 32);
                    LDSM_X4(bl[0], bl[1], bl[2], bl[3], b_loA + wko + kf * 32);
                    mma_bf16(acc[0], ah, bh[0], bh[2]);
                    mma_bf16(acc[0], ah, bl[0], bl[2]);
                    mma_bf16(acc[0], al, bh[0], bh[2]);
                    mma_bf16(acc[1], ah, bh[1], bh[3]);
                    mma_bf16(acc[1], ah, bl[1], bl[3]);
                    mma_bf16(acc[1], al, bh[1], bh[3]);
                }
            }
        }
        // ---- stash gates to smem ----
        {
            const int g = lane >> 2, tg = (lane & 3) * 2;
            #pragma unroll
            for (int nf = 0; nf < 2; nf++) {
                int col = wn * 16 + nf * 8 + tg;
                int row = wm * 16 + g;
                gs[col * 68 + row]           = acc[nf][0];
                gs[(col + 1) * 68 + row]     = acc[nf][1];
                gs[col * 68 + row + 8]       = acc[nf][2];
                gs[(col + 1) * 68 + row + 8] = acc[nf][3];
            }
        }
        __syncthreads();

        uint16_t* nhi = g_hid_hi[(s + 1) & 1];
        uint16_t* nlo = g_hid_lo[(s + 1) & 1];
        {
            float gr = gs[( 0 + h_a) * 68 + row_a] + xfa[0];
            float gf = gs[( 8 + h_a) * 68 + row_a] + xfa[1];
            float gg = gs[(16 + h_a) * 68 + row_a] + xfa[2];
            float go = gs[(24 + h_a) * 68 + row_a] + xfa[3];
            float c  = sigmoidf_(gf) * creg_a + sigmoidf_(gr) * tanhf(gg);
            creg_a = c;
            float hv = sigmoidf_(go) * tanhf(c);
            int gi = row_a * 768 + j0 + h_a;
            uint32_t b = __float_as_uint(hv);
            nhi[gi] = (uint16_t)(b >> 16);
            nlo[gi] = bf16rn(hv - __uint_as_float(b & 0xFFFF0000u));
            hsf[((size_t)s * 64 + row_a) * 768 + j0 + h_a] = hv;
        }
        {
            float gr = gs[( 0 + h_b) * 68 + row_b] + xfb[0];
            float gf = gs[( 8 + h_b) * 68 + row_b] + xfb[1];
            float gg = gs[(16 + h_b) * 68 + row_b] + xfb[2];
            float go = gs[(24 + h_b) * 68 + row_b] + xfb[3];
            float c  = sigmoidf_(gf) * creg_b + sigmoidf_(gr) * tanhf(gg);
            creg_b = c;
            float hv = sigmoidf_(go) * tanhf(c);
            int gi = row_b * 768 + j0 + h_b;
            uint32_t b = __float_as_uint(hv);
            nhi[gi] = (uint16_t)(b >> 16);
            nlo[gi] = bf16rn(hv - __uint_as_float(b & 0xFFFF0000u));
            hsf[((size_t)s * 64 + row_b) * 768 + j0 + h_b] = hv;
        }
        grid_bar(gridDim.x);
    }
}

// ---------------- backward direction ---------------------------------------------
__global__ void bwd_scan(const float* __restrict__ xb, const float* __restrict__ hTW,
                         float* __restrict__ hsb)
{
    int tid = blockIdx.x * blockDim.x + threadIdx.x;
    int h = tid % 768, b = tid / 768;
    float hr = hTW[b * 3072 + h];
    float hf = hTW[b * 3072 + 768 + h];
    float hg = hTW[b * 3072 + 1536 + h];
    float ho = hTW[b * 3072 + 2304 + h];
    float c2 = 0.f;
    for (int s = SS - 1; s >= 0; s--) {
        size_t base = ((size_t)s * 64 + b) * 3072 + h;
        float r = sigmoidf_(xb[base]          + hr);
        float f = sigmoidf_(xb[base + 768]    + hf);
        float g = tanhf    (xb[base + 1536]   + hg);
        float o = sigmoidf_(xb[base + 2304]   + ho);
        c2 = f * c2 + r * g;
        hsb[((size_t)s * 64 + b) * 768 + h] = o * tanhf(c2);
    }
}

// ---------------- output GEMM -----------------------------------------------------
__global__ void out_gemm(const float* __restrict__ hsf, const float* __restrict__ hsb,
                         const float* __restrict__ Wout, const float* __restrict__ bout,
                         const int* __restrict__ tokens, float* __restrict__ out)
{
    __shared__ __align__(16) float As[16][132];
    __shared__ __align__(16) float Bs[16][32];
    const int t  = threadIdx.x;
    const int m0 = blockIdx.y * 128;
    const int c0 = 4 * (t & 7);
    const int r0 = 4 * (t >> 3);
    const int mload = t >> 2;
    const int kq    = (t & 3) * 4;
    float acc[4][4] = {};
    for (int k0 = 0; k0 < 1536; k0 += 16) {
        const float* srcbase = (k0 < 768) ? hsf : hsb;
        int koff = (k0 < 768) ? k0 : (k0 - 768);
        #pragma unroll
        for (int half = 0; half < 2; half++) {
            int m = mload + half * 64;
            float4 v = *(const float4*)(srcbase + (size_t)(m0 + m) * 768 + koff + kq);
            As[kq + 0][m] = v.x; As[kq + 1][m] = v.y;
            As[kq + 2][m] = v.z; As[kq + 3][m] = v.w;
        }
        #pragma unroll
        for (int p = 0; p < 2; p++) {
            int idx = t + p * 256;
            int kk = idx >> 5, n = idx & 31;
            Bs[kk][n] = Wout[(size_t)(k0 + kk) * 32 + n];
        }
        __syncthreads();
        #pragma unroll
        for (int kk = 0; kk < 16; kk++) {
            float4 a = *(const float4*)&As[kk][r0];
            float4 b = *(const float4*)&Bs[kk][c0];
            acc[0][0] += a.x*b.x; acc[0][1] += a.x*b.y; acc[0][2] += a.x*b.z; acc[0][3] += a.x*b.w;
            acc[1][0] += a.y*b.x; acc[1][1] += a.y*b.y; acc[1][2] += a.y*b.z; acc[1][3] += a.y*b.w;
            acc[2][0] += a.z*b.x; acc[2][1] += a.z*b.y; acc[2][2] += a.z*b.z; acc[2][3] += a.z*b.w;
            acc[3][0] += a.w*b.x; acc[3][1] += a.w*b.y; acc[3][2] += a.w*b.z; acc[3][3] += a.w*b.w;
        }
        __syncthreads();
    }
    #pragma unroll
    for (int i = 0; i < 4; i++) {
        int m = m0 + r0 + i;
        float4 v = make_float4(acc[i][0] + bout[c0],     acc[i][1] + bout[c0 + 1],
                               acc[i][2] + bout[c0 + 2], acc[i][3] + bout[c0 + 3]);
        if (c0 == 0 && tokens[m] == 1) v.x += 10000.0f;
        *(float4*)&out[(size_t)m * 32 + c0] = v;
    }
}

// ---------------- launch ----------------------------------------------------------
extern "C" void kernel_launch(void* const* d_in, const int* in_sizes, int n_in,
                              void* d_out, int out_size)
{
    const int*   tokens    = (const int*)  d_in[0];
    const float* embedding = (const float*)d_in[2];
    const float* Wi_f      = (const float*)d_in[3];
    const float* bi_f      = (const float*)d_in[4];
    const float* Wh_f      = (const float*)d_in[5];
    const float* bh_f      = (const float*)d_in[6];
    const float* Wi_b      = (const float*)d_in[7];
    const float* bi_b      = (const float*)d_in[8];
    const float* Wh_b      = (const float*)d_in[9];
    const float* bh_b      = (const float*)d_in[10];
    const float* Wout      = (const float*)d_in[11];
    const float* bout      = (const float*)d_in[12];
    float* out = (float*)d_out;

    float *xf, *xb, *hsf, *hsb, *hTW;
    cudaGetSymbolAddress((void**)&xf,  g_xf);
    cudaGetSymbolAddress((void**)&xb,  g_xb);
    cudaGetSymbolAddress((void**)&hsf, g_hsf);
    cudaGetSymbolAddress((void**)&hsb, g_hsb);
    cudaGetSymbolAddress((void**)&hTW, g_hTW);

    cudaFuncSetAttribute(fwd_lstm_mma, cudaFuncAttributeMaxDynamicSharedMemorySize, FW_SMEM);
    cudaFuncSetAttribute(mma_gemm, cudaFuncAttributeMaxDynamicSharedMemorySize, GEMM_SMEM);

    // 1+2: input gate precompute on tensor cores (bf16x3 mma.sync)
    dim3 gG(G4 / 128, SB / 128);
    mma_gemm<<<gG, 256, GEMM_SMEM>>>(embedding, tokens, Wi_f, bi_f, bh_f, xf);
    mma_gemm<<<gG, 256, GEMM_SMEM>>>(embedding, tokens, Wi_b, nullptr, nullptr, xb);

    // 3: forward recurrence (persistent, tensor-core recurrence)
    fwd_lstm_mma<<<NBLK_FWD, 256, FW_SMEM>>>(Wh_f, xf, hsf);

    // 4: hTW = hT @ Wh_b + bi_b + bh_b
    sgemm64<<<dim3(G4 / 64, 1), 256>>>(hsf + (size_t)(SS - 1) * BB * HH, nullptr, Wh_b,
                                       BB, G4, HH, bi_b, bh_b, hTW);

    // 5: backward direction
    bwd_scan<<<(BB * HH) / 256, 256>>>(xb, hTW, hsb);

    // 6: output projection + pad bias
    out_gemm<<<dim3(1, SB / 128), 256>>>(hsf, hsb, Wout, bout, tokens, out);
}